// round 12
// baseline (speedup 1.0000x reference)
#include <cuda_runtime.h>

// Shapes (fixed): B=1024, n=C*H*W=3072, c=10, m=9
#define NN 3072
#define CC 10
#define MM 9
#define BS 4                  // samples per group
#define SPLITS 3              // n-chunks per group (1024 floats each)
#define CHUNK4 256            // float4 per chunk
#define MAX_B 8192
#define MAX_GROUPS (MAX_B / BS)

#define EPS2_INV 100.0f       // 1/EPSILON^2
#define NSTAB 1e-4f
#define SCALE 0.999f          // 1 - c*NUM_STAB

// Scratch (static device arrays — no allocation)
__device__ float g_Wt[CC * NN];                          // W transposed [c][n]
__device__ float g_M[CC * CC];                           // W^T W
__device__ float g_part[MAX_GROUPS * SPLITS * BS * CC];  // z partials
__device__ float g_reg[MAX_B];                           // per-sample reg
__device__ unsigned int g_gcnt[MAX_GROUPS];              // per-group arrival ctr
__device__ unsigned int g_fcnt = 0;                      // finalize ctr

// ---------------------------------------------------------------------------
// 1) Prep: blocks 0..29 transpose W -> Wt; blocks 30..84 compute Gram M.
__global__ void prep_kernel(const float* __restrict__ W) {
    const int blk = blockIdx.x;
    const int t = threadIdx.x;

    if (blk < 30) {
        int base = blk * 1024;
        #pragma unroll
        for (int k = 0; k < 4; k++) {
            int idx = base + t + k * 256;
            int j = idx / CC, l = idx - j * CC;
            g_Wt[l * NN + j] = W[idx];
        }
        return;
    }
    int pair = blk - 30;
    int l = 0, idx = pair;
    #pragma unroll
    for (int q = 0; q < CC; q++) {
        if (idx >= CC - q && l == q) { idx -= CC - q; l = q + 1; }
    }
    int lp = l + idx;

    float s = 0.f;
    for (int j = t; j < NN; j += 256)
        s = fmaf(W[j * CC + l], W[j * CC + lp], s);
    #pragma unroll
    for (int o = 16; o; o >>= 1) s += __shfl_xor_sync(0xffffffffu, s, o);
    __shared__ float red[8];
    if ((t & 31) == 0) red[t >> 5] = s;
    __syncthreads();
    if (t == 0) {
        float tot = 0.f;
        #pragma unroll
        for (int w = 0; w < 8; w++) tot += red[w];
        g_M[l * CC + lp] = tot;
        g_M[lp * CC + l] = tot;
    }
}

// ---------------------------------------------------------------------------
// 2) Main: grid (SPLITS, groups). Each block: one GEMV chunk for 4 samples;
//    last-arriving block per group assembles z and runs the analytic epilogue;
//    last epilogue block runs the final mean. All combines in fixed order.
__global__ __launch_bounds__(256, 3) void isometry_kernel(
    const float* __restrict__ data, const float* __restrict__ bvec,
    float* __restrict__ out, int out_size, int B, int groups) {
    const int split = blockIdx.x;            // 0..SPLITS-1
    const int group = blockIdx.y;
    const int b0 = group * BS;
    const int t = threadIdx.x;
    const int warp = t >> 5, lane = t & 31;
    const int j4 = split * CHUNK4 + t;       // float4 index in [0,768)

    // --- GEMV partial: 4 x-loads + 10 w-loads, all independent ---
    const float4* x4 = (const float4*)(data + (size_t)b0 * NN);
    const float4* w4 = (const float4*)g_Wt;

    float4 xv[BS];
    #pragma unroll
    for (int s = 0; s < BS; s++) {
        if (b0 + s < B) xv[s] = __ldcs(&x4[s * (NN / 4) + j4]);
        else            xv[s] = make_float4(0.f, 0.f, 0.f, 0.f);
    }
    float a[BS * CC];
    #pragma unroll
    for (int i = 0; i < BS * CC; i++) a[i] = 0.f;
    #pragma unroll
    for (int l = 0; l < CC; l++) {
        float4 wv = w4[l * (NN / 4) + j4];
        #pragma unroll
        for (int s = 0; s < BS; s++) {
            float v = a[s * CC + l];
            v = fmaf(xv[s].x, wv.x, v);
            v = fmaf(xv[s].y, wv.y, v);
            v = fmaf(xv[s].z, wv.z, v);
            v = fmaf(xv[s].w, wv.w, v);
            a[s * CC + l] = v;
        }
    }

    // --- warp reduce 40 values: split-exchange (rounds 1-2), naive (3-5) ---
    {
        const bool hi = (lane & 16) != 0;
        #pragma unroll
        for (int i = 0; i < 20; i++) {
            float send = hi ? a[i] : a[i + 20];
            float r = __shfl_xor_sync(0xffffffffu, send, 16);
            a[i] = (hi ? a[i + 20] : a[i]) + r;
        }
    }
    {
        const bool hi = (lane & 8) != 0;
        #pragma unroll
        for (int i = 0; i < 10; i++) {
            float send = hi ? a[i] : a[i + 10];
            float r = __shfl_xor_sync(0xffffffffu, send, 8);
            a[i] = (hi ? a[i + 10] : a[i]) + r;
        }
    }
    #pragma unroll
    for (int off = 4; off; off >>= 1) {
        #pragma unroll
        for (int i = 0; i < 10; i++)
            a[i] += __shfl_xor_sync(0xffffffffu, a[i], off);
    }
    // lanes 0,8,16,24 hold 10 final values each; value base from lane bits 4,3
    __shared__ float red[8][BS * CC];
    if ((lane & 7) == 0) {
        int vb = ((lane & 16) ? 20 : 0) + ((lane & 8) ? 10 : 0);
        #pragma unroll
        for (int i = 0; i < 10; i++) red[warp][vb + i] = a[i];
    }
    __syncthreads();

    // --- block combine, publish partial ---
    if (t < BS * CC) {
        float s = 0.f;
        #pragma unroll
        for (int w = 0; w < 8; w++) s += red[w][t];
        g_part[(group * SPLITS + split) * (BS * CC) + t] = s;
        __threadfence();
    }
    __syncthreads();

    __shared__ bool sEpi;
    if (t == 0) {
        unsigned int old = atomicInc(&g_gcnt[group], SPLITS - 1);  // self-wrap
        __threadfence();
        sEpi = (old == SPLITS - 1);
    }
    __syncthreads();
    if (!sEpi) return;

    // --- epilogue (last block of group): warps 0..3, one sample each ---
    __shared__ float z_sh[BS][CC];
    __shared__ float A_sh[BS][MM][CC];
    __shared__ float AM_sh[BS][MM][CC];

    if (warp < BS && b0 + warp < B) {
        const int smp = warp;
        if (lane < CC) {
            float zz = bvec[lane];
            #pragma unroll
            for (int sp = 0; sp < SPLITS; sp++)   // fixed order: deterministic
                zz += __ldcg(&g_part[(group * SPLITS + sp) * (BS * CC) + smp * CC + lane]);
            z_sh[smp][lane] = zz;
        }
        __syncwarp();

        float z[CC];
        #pragma unroll
        for (int l = 0; l < CC; l++) z[l] = z_sh[smp][l];
        float mz = z[0];
        #pragma unroll
        for (int l = 1; l < CC; l++) mz = fmaxf(mz, z[l]);
        float e[CC], se = 0.f;
        #pragma unroll
        for (int l = 0; l < CC; l++) { e[l] = __expf(z[l] - mz); se += e[l]; }
        float inv = 1.f / se;
        float s_[CC], r[CC];
        #pragma unroll
        for (int l = 0; l < CC; l++) {
            s_[l] = e[l] * inv;
            r[l]  = sqrtf(fmaf(s_[l], SCALE, NSTAB));
        }
        float u = 1.f - r[MM];

        float sumr = 0.f;
        #pragma unroll
        for (int l = 0; l < CC; l++) sumr += r[l];
        float arg = fminf(fmaxf(sumr * 0.31622776601683794f, -1.f), 1.f);
        float delta  = 2.f * acosf(arg);
        float factor = delta * delta / (4.f * u * u) * EPS2_INV;

        if (lane < MM) {
            int k = lane;
            float g1 = SCALE * s_[k] / (r[k] * u);
            float g2 = SCALE * r[k] * s_[MM] / (r[MM] * u * u);
            float gs = g1 + g2;
            #pragma unroll
            for (int l = 0; l < CC; l++) {
                float A = -s_[l] * gs;
                if (l == k)  A += g1;
                if (l == MM) A += g2;
                A_sh[smp][k][l] = A;
            }
        }
        __syncwarp();
        if (lane < MM) {
            #pragma unroll
            for (int lp = 0; lp < CC; lp++) {
                float v = 0.f;
                #pragma unroll
                for (int l = 0; l < CC; l++)
                    v = fmaf(A_sh[smp][lane][l], g_M[l * CC + lp], v);
                AM_sh[smp][lane][lp] = v;
            }
        }
        __syncwarp();

        float ss = 0.f;
        for (int idx = lane; idx < MM * MM; idx += 32) {
            int i = idx / MM, j = idx - i * MM;
            float g = 0.f;
            #pragma unroll
            for (int l = 0; l < CC; l++)
                g = fmaf(AM_sh[smp][i][l], A_sh[smp][j][l], g);
            if (i == j) g -= factor;
            ss = fmaf(g, g, ss);
        }
        #pragma unroll
        for (int o = 16; o; o >>= 1) ss += __shfl_xor_sync(0xffffffffu, ss, o);
        if (lane == 0) {
            g_reg[b0 + smp] = sqrtf(ss) * (1.0f / (float)NN);
            __threadfence();
        }
    }
    __syncthreads();

    // --- fused finalize: last epilogue block reduces g_reg deterministically ---
    __shared__ bool sFin;
    if (t == 0) {
        unsigned int old = atomicInc(&g_fcnt, (unsigned)groups - 1);  // self-wrap
        __threadfence();
        sFin = (old == (unsigned)groups - 1);
    }
    __syncthreads();
    if (!sFin) return;

    __shared__ float fred[8];
    float s = 0.f;
    for (int i = t; i < B; i += 256) s += __ldcg(&g_reg[i]);
    #pragma unroll
    for (int o = 16; o; o >>= 1) s += __shfl_xor_sync(0xffffffffu, s, o);
    if ((t & 31) == 0) fred[t >> 5] = s;
    __syncthreads();
    if (t == 0) {
        float tot = 0.f;
        #pragma unroll
        for (int w = 0; w < 8; w++) tot += fred[w];
        out[0] = tot / (float)B;
    }
    for (int i = 1 + t; i < out_size; i += 256) out[i] = 0.0f;
}

// ---------------------------------------------------------------------------
extern "C" void kernel_launch(void* const* d_in, const int* in_sizes, int n_in,
                              void* d_out, int out_size) {
    const float* data = (const float*)d_in[0];   // [B, 3, 32, 32]
    const float* W    = (const float*)d_in[1];   // [3072, 10]
    const float* bvec = (const float*)d_in[2];   // [10]
    float* out = (float*)d_out;

    int B = in_sizes[0] / NN;
    if (B > MAX_B) B = MAX_B;
    int groups = (B + BS - 1) / BS;

    prep_kernel<<<30 + (CC * (CC + 1)) / 2, 256>>>(W);
    dim3 grid(SPLITS, groups);
    isometry_kernel<<<grid, 256>>>(data, bvec, out, out_size, B, groups);
}